// round 13
// baseline (speedup 1.0000x reference)
#include <cuda_runtime.h>
#include <cuda_fp16.h>
#include <cstdint>

// ---------------------------------------------------------------------------
// EncoderByType (GB300, compute_103): fp16 m16n8k16 mma.sync GEMM.
// Round 13: r11 config (CTA 128x128x64, 256 thr, 8 warps 4m x 2n, warp 32x64,
// 3-stage cp.async ring, 2 CTAs/SM) + fragment double-buffering under a hard
// 128-reg cap (acc 64 + frags 48 fits). fp16 activations, padded tiles.
// ---------------------------------------------------------------------------

__device__ __half g_x [32014336];          // padded fp16 inputs
__device__ __half g_h1[240128ll * 512];
__device__ __half g_h2[240128ll * 512];
__device__ __half g_Wt[1409024];           // 9 weights, [N,K] fp16

// ------------------------- helpers -----------------------------------------
__device__ __forceinline__ uint32_t smem_u32(const void* p) {
    uint32_t a;
    asm("{ .reg .u64 t; cvta.to.shared.u64 t, %1; cvt.u32.u64 %0, t; }"
        : "=r"(a) : "l"(p));
    return a;
}
__device__ __forceinline__ float fast_sigmoid(float x) {
    float t;
    asm("tanh.approx.f32 %0, %1;" : "=f"(t) : "f"(0.5f * x));
    return fmaf(0.5f, t, 0.5f);
}
__device__ __forceinline__ uint32_t packh2(float lo, float hi) {
    __half2 h = __floats2half2_rn(lo, hi);
    return *reinterpret_cast<uint32_t*>(&h);
}
__device__ __forceinline__ void mma_fp16(float* d, const uint4& a,
                                         uint32_t b0, uint32_t b1) {
    asm volatile(
        "mma.sync.aligned.m16n8k16.row.col.f32.f16.f16.f32 "
        "{%0,%1,%2,%3}, {%4,%5,%6,%7}, {%8,%9}, {%0,%1,%2,%3};"
        : "+f"(d[0]), "+f"(d[1]), "+f"(d[2]), "+f"(d[3])
        : "r"(a.x), "r"(a.y), "r"(a.z), "r"(a.w), "r"(b0), "r"(b1));
}
__device__ __forceinline__ void ldsm4(uint4& d, uint32_t addr) {
    asm volatile(
        "ldmatrix.sync.aligned.m8n8.x4.shared.b16 {%0,%1,%2,%3}, [%4];"
        : "=r"(d.x), "=r"(d.y), "=r"(d.z), "=r"(d.w) : "r"(addr));
}
#define CP_ASYNC16(dst, src) \
    asm volatile("cp.async.cg.shared.global [%0], [%1], 16;" :: "r"(dst), "l"(src))
#define CP_COMMIT() asm volatile("cp.async.commit_group;" ::: "memory")
#define CP_WAIT(n)  asm volatile("cp.async.wait_group %0;" :: "n"(n) : "memory")

// ------------------------- weight transpose+convert ------------------------
struct TransArgs {
    const float* W[9];
    long long wtoff[9];
    int K[9];
    int N[9];
    int tbase[10];
};

__global__ void __launch_bounds__(256)
transpose_weights(TransArgs a) {
    int m = 0;
    while ((int)blockIdx.x >= a.tbase[m + 1]) m++;
    int t = blockIdx.x - a.tbase[m];
    int Km = a.K[m], Nm = a.N[m];
    int tilesN = Nm >> 5;
    int tk = t / tilesN, tn = t % tilesN;

    __shared__ float tile[32][33];
    int tx = threadIdx.x & 31, ty0 = threadIdx.x >> 5;
    const float* W = a.W[m];
#pragma unroll
    for (int i = 0; i < 4; i++) {
        int ty = ty0 + i * 8;
        tile[ty][tx] = W[(long long)(tk * 32 + ty) * Nm + tn * 32 + tx];
    }
    __syncthreads();
    __half* Wt = g_Wt + a.wtoff[m];
#pragma unroll
    for (int i = 0; i < 4; i++) {
        int ty = ty0 + i * 8;
        Wt[(long long)(tn * 32 + ty) * Km + tk * 32 + tx] = __float2half(tile[tx][ty]);
    }
}

// ------------------------- input convert (all 3 in one launch) -------------
__global__ void __launch_bounds__(256)
cvt_all(const float* s0, const float* s1, const float* s2,
        __half* d0, __half* d1, __half* d2, int c1, int c2, int c3)
{
    int i = blockIdx.x * 256 + threadIdx.x;
    if (i >= c3) return;
    const float* s;
    __half* d;
    int j;
    if (i < c1)      { s = s0; d = d0; j = i; }
    else if (i < c2) { s = s1; d = d1; j = i - c1; }
    else             { s = s2; d = d2; j = i - c2; }
    float4 v = ((const float4*)s)[j];
    uint2 o;
    o.x = packh2(v.x, v.y);
    o.y = packh2(v.z, v.w);
    ((uint2*)d)[j] = o;
}

// ------------------------- fused layer kernel ------------------------------
// Grid: (N/128, sum_tiles). CTA 256 threads = 8 warps (4m x 2n), warp 32x64.
// Smem: 3 stages x (A 16KB + B 16KB) = 96KB. BK = 64 halfs (128B rows),
// XOR swizzle: 16B chunk c stored at c ^ (row & 7).
struct LArgs {
    const __half* A[3];
    void* C[3];
    const float* bias[3];
    const __half* Wt[3];
    int M[3], K[3];
    int tb[4];
    int N;
};

template <bool CF32>
__global__ void __launch_bounds__(256, 2)
mlp_layer(LArgs a)
{
    extern __shared__ char smem[];
    const int t = ((int)blockIdx.y >= a.tb[1]) + ((int)blockIdx.y >= a.tb[2]);
    const int K = a.K[t];
    const int N = a.N;
    const long long bm = (long long)((int)blockIdx.y - a.tb[t]) * 128;
    const int bn = blockIdx.x * 128;
    const __half* Ah = a.A[t];
    const __half* Wt = a.Wt[t];
    const int KT = K >> 6;

    const int tid = threadIdx.x;
    const int lane = tid & 31;
    const int wid = tid >> 5;
    const int warp_m = wid & 3;     // 4 m-warps of 32 rows
    const int warp_n = wid >> 2;    // 2 n-warps of 64 cols

    const uint32_t sb = smem_u32(smem);

    // ---- cp.async maps: 256 thr x 8 chunks ----
    const int crow = tid >> 3;          // 0..31 (+ i*32)
    const int cchk = tid & 7;
    const __half* pA = Ah + (bm + crow) * (long long)K + cchk * 8;
    const __half* pB = Wt + (long long)(bn + crow) * K + cchk * 8;
    const uint32_t swz = (uint32_t)((cchk ^ (crow & 7)) * 16);
    const uint32_t dA = sb + crow * 128 + swz;
    const uint32_t dB = sb + 16384 + crow * 128 + swz;
    const long long rstep = 32ll * K;   // halfs per 32 rows

    // ---- ldmatrix address bases ----
    const int l15 = lane & 15;
    const int ahi = lane >> 4;
    const uint32_t aX = (uint32_t)(lane & 7);
    const uint32_t aBase = sb + (uint32_t)(warp_m * 32 + l15) * 128;
    const int bn_l = warp_n * 64 + ((lane >> 4) << 3) + (lane & 7);
    const int bhi = (lane >> 3) & 1;
    const uint32_t bBase = sb + 16384 + (uint32_t)bn_l * 128;

    float acc[2][8][4];
#pragma unroll
    for (int i = 0; i < 2; i++)
#pragma unroll
        for (int j = 0; j < 8; j++)
#pragma unroll
            for (int q = 0; q < 4; q++) acc[i][j][q] = 0.0f;

    uint4 afr[2][2], bfr[2][4];

#define ISSUE(kt, slot)                                                      \
    do {                                                                     \
        const __half* sA_ = pA + (kt) * 64;                                  \
        const __half* sB_ = pB + (kt) * 64;                                  \
        uint32_t oA_ = dA + (slot) * 32768u;                                 \
        uint32_t oB_ = dB + (slot) * 32768u;                                 \
        _Pragma("unroll")                                                    \
        for (int i = 0; i < 4; i++)                                          \
            CP_ASYNC16(oA_ + i * 4096u, sA_ + i * rstep);                    \
        _Pragma("unroll")                                                    \
        for (int i = 0; i < 4; i++)                                          \
            CP_ASYNC16(oB_ + i * 4096u, sB_ + i * rstep);                    \
    } while (0)

#define LOAD_FRAGS(aS_, bS_, s_, pb_)                                        \
    do {                                                                     \
        _Pragma("unroll")                                                    \
        for (int mt = 0; mt < 2; mt++)                                       \
            ldsm4(afr[pb_][mt], (aS_) + mt * 2048u +                         \
                  ((((uint32_t)(2 * (s_) + ahi)) ^ aX) << 4));               \
        _Pragma("unroll")                                                    \
        for (int ng = 0; ng < 4; ng++)                                       \
            ldsm4(bfr[pb_][ng], (bS_) + ng * 2048u +                         \
                  ((((uint32_t)(2 * (s_) + bhi)) ^ aX) << 4));               \
    } while (0)

    // ---- prologue: fill 2 stages ----
    ISSUE(0, 0);
    CP_COMMIT();
    if (1 < KT) ISSUE(1, 1);
    CP_COMMIT();

    CP_WAIT(1);
    __syncthreads();
    uint32_t aS = aBase, bS = bBase;
    LOAD_FRAGS(aS, bS, 0, 0);

    int pf = 2;
    for (int kt = 0; kt < KT; kt++) {
        if (pf < KT) {
            int slot = pf - (pf / 3) * 3;
            ISSUE(pf, slot);
        }
        CP_COMMIT();
        pf++;

#pragma unroll
        for (int s = 0; s < 4; s++) {
            const int cb = s & 1;
            if (s < 3) LOAD_FRAGS(aS, bS, s + 1, cb ^ 1);
#pragma unroll
            for (int mt = 0; mt < 2; mt++)
#pragma unroll
                for (int ng = 0; ng < 4; ng++) {
                    mma_fp16(acc[mt][2 * ng],     afr[cb][mt], bfr[cb][ng].x, bfr[cb][ng].y);
                    mma_fp16(acc[mt][2 * ng + 1], afr[cb][mt], bfr[cb][ng].z, bfr[cb][ng].w);
                }
        }
        if (kt + 1 < KT) {
            CP_WAIT(1);
            __syncthreads();
            const int cur = (kt + 1) - ((kt + 1) / 3) * 3;
            aS = aBase + cur * 32768u;
            bS = bBase + cur * 32768u;
            LOAD_FRAGS(aS, bS, 0, 0);
        }
    }
#undef ISSUE
#undef LOAD_FRAGS

    // ---- epilogue: bias + sigmoid ----
    const float* bias = a.bias[t];
    const int M = a.M[t];
#pragma unroll
    for (int mt = 0; mt < 2; mt++) {
        long long r0 = bm + warp_m * 32 + mt * 16 + (lane >> 2);
        long long r1 = r0 + 8;
#pragma unroll
        for (int np = 0; np < 8; np++) {
            int n = bn + warp_n * 64 + np * 8 + 2 * (lane & 3);
            float2 bv = *(const float2*)(bias + n);
            float* d = acc[mt][np];
            float s0 = fast_sigmoid(d[0] + bv.x);
            float s1 = fast_sigmoid(d[1] + bv.y);
            float s2 = fast_sigmoid(d[2] + bv.x);
            float s3 = fast_sigmoid(d[3] + bv.y);
            if (CF32) {
                float* C = (float*)a.C[t];
                if (r0 < M) *(float2*)(C + r0 * N + n) = make_float2(s0, s1);
                if (r1 < M) *(float2*)(C + r1 * N + n) = make_float2(s2, s3);
            } else {
                __half* C = (__half*)a.C[t];
                *(uint32_t*)(C + r0 * N + n) = packh2(s0, s1);
                *(uint32_t*)(C + r1 * N + n) = packh2(s2, s3);
            }
        }
    }
}

// ------------------------- host launcher -----------------------------------
extern "C" void kernel_launch(void* const* d_in, const int* in_sizes, int n_in,
                              void* d_out, int out_size)
{
    (void)n_in; (void)out_size;
    const int din[3] = {64, 128, 256};
    int n[3];
    for (int t = 0; t < 3; t++) n[t] = in_sizes[t] / din[t];

    int tiles[3], tb[4];
    tb[0] = 0;
    for (int t = 0; t < 3; t++) {
        tiles[t] = (n[t] + 127) / 128;
        tb[t + 1] = tb[t] + tiles[t];
    }
    long long padrows[3] = {(long long)tiles[0] * 128, (long long)tiles[1] * 128,
                            (long long)tiles[2] * 128};
    long long hb[3] = {0, padrows[0], padrows[0] + padrows[1]};
    long long xoff[3] = {0, padrows[0] * din[0],
                         padrows[0] * din[0] + padrows[1] * din[1]};
    long long outbase[3] = {0, n[0], (long long)n[0] + n[1]};

    const int SMEM = 3 * 32768;   // 98304
    static int attr_done = 0;
    if (!attr_done) {
        cudaFuncSetAttribute(mlp_layer<false>,
                             cudaFuncAttributeMaxDynamicSharedMemorySize, SMEM);
        cudaFuncSetAttribute(mlp_layer<true>,
                             cudaFuncAttributeMaxDynamicSharedMemorySize, SMEM);
        attr_done = 1;
    }

    // ---- transpose + fp16-convert all weights ----
    TransArgs ta;
    long long woff[9];
    {
        long long w = 0;
        int tbt = 0;
        for (int t = 0; t < 3; t++) {
            int Ks[3] = {din[t], 512, 512};
            int Ns[3] = {512, 512, 256};
            for (int l = 0; l < 3; l++) {
                int idx = t * 3 + l;
                ta.W[idx] = (const float*)d_in[4 + 6 * t + 2 * l];
                ta.wtoff[idx] = w;
                woff[idx] = w;
                ta.K[idx] = Ks[l];
                ta.N[idx] = Ns[l];
                ta.tbase[idx] = tbt;
                tbt += (Ks[l] / 32) * (Ns[l] / 32);
                w += (long long)Ks[l] * Ns[l];
            }
        }
        ta.tbase[9] = tbt;
        transpose_weights<<<tbt, 256>>>(ta);
    }

    __half *xh, *h1, *h2, *wt;
    cudaGetSymbolAddress((void**)&xh, g_x);
    cudaGetSymbolAddress((void**)&h1, g_h1);
    cudaGetSymbolAddress((void**)&h2, g_h2);
    cudaGetSymbolAddress((void**)&wt, g_Wt);

    // ---- convert inputs to padded fp16 (one launch) ----
    {
        int c1 = n[0] * din[0] / 4;
        int c2 = c1 + n[1] * din[1] / 4;
        int c3 = c2 + n[2] * din[2] / 4;
        cvt_all<<<(c3 + 255) / 256, 256>>>(
            (const float*)d_in[0], (const float*)d_in[1], (const float*)d_in[2],
            xh + xoff[0], xh + xoff[1], xh + xoff[2], c1, c2, c3);
    }

    // ---- layer launches ----
    LArgs a;
    for (int i = 0; i < 4; i++) a.tb[i] = tb[i];

    a.N = 512;
    for (int t = 0; t < 3; t++) {
        a.A[t] = xh + xoff[t];
        a.C[t] = h1 + hb[t] * 512;
        a.bias[t] = (const float*)d_in[5 + 6 * t];
        a.Wt[t] = wt + woff[t * 3 + 0];
        a.M[t] = n[t];
        a.K[t] = din[t];
    }
    mlp_layer<false><<<dim3(4, tb[3]), 256, SMEM>>>(a);

    for (int t = 0; t < 3; t++) {
        a.A[t] = h1 + hb[t] * 512;
        a.C[t] = h2 + hb[t] * 512;
        a.bias[t] = (const float*)d_in[7 + 6 * t];
        a.Wt[t] = wt + woff[t * 3 + 1];
        a.M[t] = n[t];
        a.K[t] = 512;
    }
    mlp_layer<false><<<dim3(4, tb[3]), 256, SMEM>>>(a);

    a.N = 256;
    for (int t = 0; t < 3; t++) {
        a.A[t] = h2 + hb[t] * 512;
        a.C[t] = (float*)d_out + outbase[t] * 256;
        a.bias[t] = (const float*)d_in[9 + 6 * t];
        a.Wt[t] = wt + woff[t * 3 + 2];
        a.M[t] = n[t];
        a.K[t] = 512;
    }
    mlp_layer<true><<<dim3(2, tb[3]), 256, SMEM>>>(a);
}

// round 14
// speedup vs baseline: 1.5046x; 1.5046x over previous
#include <cuda_runtime.h>
#include <cuda_fp16.h>
#include <cstdint>

// ---------------------------------------------------------------------------
// EncoderByType (GB300, compute_103): fp16 m16n8k16 mma.sync GEMM.
// Round 14: layers 2/3 = exact r11 kernel (best known: 60% tensor, 2 CTAs/SM).
// Layer 1 = dedicated full-resident kernel: A+B fully staged (<=128KB), one
// cp.async wait, barrier-free compute with fragment double-buffering.
// transpose+cvt merged into one prep launch.
// ---------------------------------------------------------------------------

__device__ __half g_x [32014336];          // padded fp16 inputs
__device__ __half g_h1[240128ll * 512];
__device__ __half g_h2[240128ll * 512];
__device__ __half g_Wt[1409024];           // 9 weights, [N,K] fp16

// ------------------------- helpers -----------------------------------------
__device__ __forceinline__ uint32_t smem_u32(const void* p) {
    uint32_t a;
    asm("{ .reg .u64 t; cvta.to.shared.u64 t, %1; cvt.u32.u64 %0, t; }"
        : "=r"(a) : "l"(p));
    return a;
}
__device__ __forceinline__ float fast_sigmoid(float x) {
    float t;
    asm("tanh.approx.f32 %0, %1;" : "=f"(t) : "f"(0.5f * x));
    return fmaf(0.5f, t, 0.5f);
}
__device__ __forceinline__ uint32_t packh2(float lo, float hi) {
    __half2 h = __floats2half2_rn(lo, hi);
    return *reinterpret_cast<uint32_t*>(&h);
}
__device__ __forceinline__ void mma_fp16(float* d, const uint4& a,
                                         uint32_t b0, uint32_t b1) {
    asm volatile(
        "mma.sync.aligned.m16n8k16.row.col.f32.f16.f16.f32 "
        "{%0,%1,%2,%3}, {%4,%5,%6,%7}, {%8,%9}, {%0,%1,%2,%3};"
        : "+f"(d[0]), "+f"(d[1]), "+f"(d[2]), "+f"(d[3])
        : "r"(a.x), "r"(a.y), "r"(a.z), "r"(a.w), "r"(b0), "r"(b1));
}
__device__ __forceinline__ void ldsm4(uint4& d, uint32_t addr) {
    asm volatile(
        "ldmatrix.sync.aligned.m8n8.x4.shared.b16 {%0,%1,%2,%3}, [%4];"
        : "=r"(d.x), "=r"(d.y), "=r"(d.z), "=r"(d.w) : "r"(addr));
}
#define CP_ASYNC16(dst, src) \
    asm volatile("cp.async.cg.shared.global [%0], [%1], 16;" :: "r"(dst), "l"(src))
#define CP_COMMIT() asm volatile("cp.async.commit_group;" ::: "memory")
#define CP_WAIT(n)  asm volatile("cp.async.wait_group %0;" :: "n"(n) : "memory")

// ------------------------- prep: transpose + cvt in one launch -------------
struct PrepArgs {
    const float* W[9];
    long long wtoff[9];
    int K[9];
    int N[9];
    int tbase[10];
    const float* xs[3];
    __half* xd[3];
    int c1, c2, c3;      // cumulative float4 counts
};

__global__ void __launch_bounds__(256)
prep_kernel(PrepArgs a) {
    if ((int)blockIdx.x < a.tbase[9]) {
        // ---- weight transpose+convert ----
        int m = 0;
        while ((int)blockIdx.x >= a.tbase[m + 1]) m++;
        int t = blockIdx.x - a.tbase[m];
        int Km = a.K[m], Nm = a.N[m];
        int tilesN = Nm >> 5;
        int tk = t / tilesN, tn = t % tilesN;

        __shared__ float tile[32][33];
        int tx = threadIdx.x & 31, ty0 = threadIdx.x >> 5;
        const float* W = a.W[m];
#pragma unroll
        for (int i = 0; i < 4; i++) {
            int ty = ty0 + i * 8;
            tile[ty][tx] = W[(long long)(tk * 32 + ty) * Nm + tn * 32 + tx];
        }
        __syncthreads();
        __half* Wt = g_Wt + a.wtoff[m];
#pragma unroll
        for (int i = 0; i < 4; i++) {
            int ty = ty0 + i * 8;
            Wt[(long long)(tn * 32 + ty) * Km + tk * 32 + tx] = __float2half(tile[tx][ty]);
        }
    } else {
        // ---- input fp32 -> fp16 ----
        int i = ((int)blockIdx.x - a.tbase[9]) * 256 + threadIdx.x;
        if (i >= a.c3) return;
        const float* s;
        __half* d;
        int j;
        if (i < a.c1)      { s = a.xs[0]; d = a.xd[0]; j = i; }
        else if (i < a.c2) { s = a.xs[1]; d = a.xd[1]; j = i - a.c1; }
        else               { s = a.xs[2]; d = a.xd[2]; j = i - a.c2; }
        float4 v = ((const float4*)s)[j];
        uint2 o;
        o.x = packh2(v.x, v.y);
        o.y = packh2(v.z, v.w);
        ((uint2*)d)[j] = o;
    }
}

// ------------------------- layer-1 kernel (full-resident) ------------------
// K in {64,128,256}: A tile 128xK and B tile 128xK both staged completely.
// Grid (4, tiles). 256 thr = 8 warps (4m x 2n), warp 32x64. N = 512.
// Row chunks swizzled: phys = (ck & ~7) | ((ck ^ (row & 7)) & 7).
struct L1Args {
    const __half* A[3];
    __half* C[3];
    const float* bias[3];
    const __half* Wt[3];
    int M[3], K[3];
    int tb[4];
};

__global__ void __launch_bounds__(256, 1)
mlp_l1(L1Args a)
{
    extern __shared__ char smem[];
    const int t = ((int)blockIdx.y >= a.tb[1]) + ((int)blockIdx.y >= a.tb[2]);
    const int K = a.K[t];
    const long long bm = (long long)((int)blockIdx.y - a.tb[t]) * 128;
    const int bn = blockIdx.x * 128;
    const __half* Ah = a.A[t];
    const __half* Wt = a.Wt[t];
    const int KT = K >> 6;
    const int lgC = (K == 64) ? 3 : (K == 128 ? 4 : 5);
    const int CPR = 1 << lgC;

    const int tid = threadIdx.x;
    const int lane = tid & 31;
    const int wid = tid >> 5;
    const int warp_m = wid & 3;
    const int warp_n = wid >> 2;

    const uint32_t sb = smem_u32(smem);
    const uint32_t bufA = sb;
    const uint32_t bufB = sb + 65536;

    // ---- stage all of A and B ----
    {
        const int total = 128 << lgC;    // chunks per tile
        for (int idx = tid; idx < total; idx += 256) {
            const int row = idx >> lgC;
            const int ck = idx & (CPR - 1);
            const int phys = (ck & ~7) | ((ck ^ row) & 7);
            const uint32_t off = ((uint32_t)idx - ck + phys) << 4;
            CP_ASYNC16(bufA + off, Ah + (bm + row) * (long long)K + ck * 8);
            CP_ASYNC16(bufB + off, Wt + (long long)(bn + row) * K + ck * 8);
        }
    }
    CP_COMMIT();
    CP_WAIT(0);
    __syncthreads();

    // ---- fragment addressing ----
    const int l15 = lane & 15;
    const int ahi = lane >> 4;
    const int lx = lane & 7;
    const int brow_l = ((lane >> 4) << 3) + lx;
    const int bhi = (lane >> 3) & 1;
    const uint32_t aRow = bufA + ((uint32_t)(warp_m * 32 + l15) << (lgC + 4));
    const uint32_t bRow = bufB + ((uint32_t)(warp_n * 64 + brow_l) << (lgC + 4));

    float acc[2][8][4];
#pragma unroll
    for (int i = 0; i < 2; i++)
#pragma unroll
        for (int j = 0; j < 8; j++)
#pragma unroll
            for (int q = 0; q < 4; q++) acc[i][j][q] = 0.0f;

    uint4 afr[2][2], bfr[2][4];

#define L1_FRAGS(st_, pb_)                                                    \
    do {                                                                      \
        const int cka_ = 2 * (st_) + ahi;                                     \
        const int ckb_ = 2 * (st_) + bhi;                                     \
        const uint32_t pa_ = (uint32_t)((cka_ & ~7) | ((cka_ ^ lx) & 7)) << 4;\
        const uint32_t pb2_ = (uint32_t)((ckb_ & ~7) | ((ckb_ ^ lx) & 7)) << 4;\
        _Pragma("unroll")                                                     \
        for (int mt = 0; mt < 2; mt++)                                        \
            ldsm4(afr[pb_][mt], aRow + ((uint32_t)(mt * 16) << (lgC + 4)) + pa_);\
        _Pragma("unroll")                                                     \
        for (int ng = 0; ng < 4; ng++)                                        \
            ldsm4(bfr[pb_][ng], bRow + ((uint32_t)(ng * 16) << (lgC + 4)) + pb2_);\
    } while (0)

    const int ST = 4 * KT;
    L1_FRAGS(0, 0);
    for (int st = 0; st < ST; st++) {
        const int cb = st & 1;
        if (st + 1 < ST) L1_FRAGS(st + 1, cb ^ 1);
#pragma unroll
        for (int mt = 0; mt < 2; mt++)
#pragma unroll
            for (int ng = 0; ng < 4; ng++) {
                mma_fp16(acc[mt][2 * ng],     afr[cb][mt], bfr[cb][ng].x, bfr[cb][ng].y);
                mma_fp16(acc[mt][2 * ng + 1], afr[cb][mt], bfr[cb][ng].z, bfr[cb][ng].w);
            }
    }
#undef L1_FRAGS

    // ---- epilogue: bias + sigmoid -> fp16 h1 ----
    const float* bias = a.bias[t];
    __half* C = a.C[t];
#pragma unroll
    for (int mt = 0; mt < 2; mt++) {
        long long r0 = bm + warp_m * 32 + mt * 16 + (lane >> 2);
        long long r1 = r0 + 8;
#pragma unroll
        for (int np = 0; np < 8; np++) {
            int n = bn + warp_n * 64 + np * 8 + 2 * (lane & 3);
            float2 bv = *(const float2*)(bias + n);
            float* d = acc[mt][np];
            *(uint32_t*)(C + r0 * 512 + n) =
                packh2(fast_sigmoid(d[0] + bv.x), fast_sigmoid(d[1] + bv.y));
            *(uint32_t*)(C + r1 * 512 + n) =
                packh2(fast_sigmoid(d[2] + bv.x), fast_sigmoid(d[3] + bv.y));
        }
    }
}

// ------------------------- layers 2/3 kernel (r11, unchanged) --------------
struct LArgs {
    const __half* A[3];
    void* C[3];
    const float* bias[3];
    const __half* Wt[3];
    int M[3], K[3];
    int tb[4];
    int N;
};

template <bool CF32>
__global__ void __launch_bounds__(256, 2)
mlp_layer(LArgs a)
{
    extern __shared__ char smem[];
    const int t = ((int)blockIdx.y >= a.tb[1]) + ((int)blockIdx.y >= a.tb[2]);
    const int K = a.K[t];
    const int N = a.N;
    const long long bm = (long long)((int)blockIdx.y - a.tb[t]) * 128;
    const int bn = blockIdx.x * 128;
    const __half* Ah = a.A[t];
    const __half* Wt = a.Wt[t];
    const int KT = K >> 6;

    const int tid = threadIdx.x;
    const int lane = tid & 31;
    const int wid = tid >> 5;
    const int warp_m = wid & 3;
    const int warp_n = wid >> 2;

    const uint32_t sb = smem_u32(smem);

    const int crow = tid >> 3;
    const int cchk = tid & 7;
    const __half* pA = Ah + (bm + crow) * (long long)K + cchk * 8;
    const __half* pB = Wt + (long long)(bn + crow) * K + cchk * 8;
    const uint32_t swz = (uint32_t)((cchk ^ (crow & 7)) * 16);
    const uint32_t dA = sb + crow * 128 + swz;
    const uint32_t dB = sb + 16384 + crow * 128 + swz;
    const long long rstep = 32ll * K;

    const int l15 = lane & 15;
    const int ahi = lane >> 4;
    const uint32_t aX = (uint32_t)(lane & 7);
    const uint32_t aBase = sb + (uint32_t)(warp_m * 32 + l15) * 128;
    const int bn_l = warp_n * 64 + ((lane >> 4) << 3) + (lane & 7);
    const int bhi = (lane >> 3) & 1;
    const uint32_t bBase = sb + 16384 + (uint32_t)bn_l * 128;

    float acc[2][8][4];
#pragma unroll
    for (int i = 0; i < 2; i++)
#pragma unroll
        for (int j = 0; j < 8; j++)
#pragma unroll
            for (int q = 0; q < 4; q++) acc[i][j][q] = 0.0f;

#define ISSUE(kt, slot)                                                      \
    do {                                                                     \
        const __half* sA_ = pA + (kt) * 64;                                  \
        const __half* sB_ = pB + (kt) * 64;                                  \
        uint32_t oA_ = dA + (slot) * 32768u;                                 \
        uint32_t oB_ = dB + (slot) * 32768u;                                 \
        _Pragma("unroll")                                                    \
        for (int i = 0; i < 4; i++)                                          \
            CP_ASYNC16(oA_ + i * 4096u, sA_ + i * rstep);                    \
        _Pragma("unroll")                                                    \
        for (int i = 0; i < 4; i++)                                          \
            CP_ASYNC16(oB_ + i * 4096u, sB_ + i * rstep);                    \
    } while (0)

    ISSUE(0, 0);
    CP_COMMIT();
    if (1 < KT) ISSUE(1, 1);
    CP_COMMIT();

    int pf = 2;
    for (int kt = 0; kt < KT; kt++) {
        CP_WAIT(1);
        __syncthreads();
        if (pf < KT) {
            int slot = pf - (pf / 3) * 3;
            ISSUE(pf, slot);
        }
        CP_COMMIT();
        pf++;

        const int cur = kt - (kt / 3) * 3;
        const uint32_t aS = aBase + cur * 32768u;
        const uint32_t bS = bBase + cur * 32768u;
#pragma unroll
        for (int s = 0; s < 4; s++) {
            uint4 af[2];
#pragma unroll
            for (int mt = 0; mt < 2; mt++)
                ldsm4(af[mt], aS + mt * 2048u + ((((uint32_t)(2 * s + ahi)) ^ aX) << 4));
            uint4 bf[4];
#pragma unroll
            for (int ng = 0; ng < 4; ng++)
                ldsm4(bf[ng], bS + ng * 2048u + ((((uint32_t)(2 * s + bhi)) ^ aX) << 4));
#pragma unroll
            for (int mt = 0; mt < 2; mt++)
#pragma unroll
                for (int ng = 0; ng < 4; ng++) {
                    mma_fp16(acc[mt][2 * ng],     af[mt], bf[ng].x, bf[ng].y);
                    mma_fp16(acc[mt][2 * ng + 1], af[mt], bf[ng].z, bf[ng].w);
                }
        }
    }
#undef ISSUE

    const float* bias = a.bias[t];
    const int M = a.M[t];
#pragma unroll
    for (int mt = 0; mt < 2; mt++) {
        long long r0 = bm + warp_m * 32 + mt * 16 + (lane >> 2);
        long long r1 = r0 + 8;
#pragma unroll
        for (int np = 0; np < 8; np++) {
            int n = bn + warp_n * 64 + np * 8 + 2 * (lane & 3);
            float2 bv = *(const float2*)(bias + n);
            float* d = acc[mt][np];
            float s0 = fast_sigmoid(d[0] + bv.x);
            float s1 = fast_sigmoid(d[1] + bv.y);
            float s2 = fast_sigmoid(d[2] + bv.x);
            float s3 = fast_sigmoid(d[3] + bv.y);
            if (CF32) {
                float* C = (float*)a.C[t];
                if (r0 < M) *(float2*)(C + r0 * N + n) = make_float2(s0, s1);
                if (r1 < M) *(float2*)(C + r1 * N + n) = make_float2(s2, s3);
            } else {
                __half* C = (__half*)a.C[t];
                *(uint32_t*)(C + r0 * N + n) = packh2(s0, s1);
                *(uint32_t*)(C + r1 * N + n) = packh2(s2, s3);
            }
        }
    }
}

// ------------------------- host launcher -----------------------------------
extern "C" void kernel_launch(void* const* d_in, const int* in_sizes, int n_in,
                              void* d_out, int out_size)
{
    (void)n_in; (void)out_size;
    const int din[3] = {64, 128, 256};
    int n[3];
    for (int t = 0; t < 3; t++) n[t] = in_sizes[t] / din[t];

    int tiles[3], tb[4];
    tb[0] = 0;
    for (int t = 0; t < 3; t++) {
        tiles[t] = (n[t] + 127) / 128;
        tb[t + 1] = tb[t] + tiles[t];
    }
    long long padrows[3] = {(long long)tiles[0] * 128, (long long)tiles[1] * 128,
                            (long long)tiles[2] * 128};
    long long hb[3] = {0, padrows[0], padrows[0] + padrows[1]};
    long long xoff[3] = {0, padrows[0] * din[0],
                         padrows[0] * din[0] + padrows[1] * din[1]};
    long long outbase[3] = {0, n[0], (long long)n[0] + n[1]};

    const int SMEM = 3 * 32768;      // layers 2/3
    const int SMEM_L1 = 131072;      // layer 1 full-resident
    static int attr_done = 0;
    if (!attr_done) {
        cudaFuncSetAttribute(mlp_layer<false>,
                             cudaFuncAttributeMaxDynamicSharedMemorySize, SMEM);
        cudaFuncSetAttribute(mlp_layer<true>,
                             cudaFuncAttributeMaxDynamicSharedMemorySize, SMEM);
        cudaFuncSetAttribute(mlp_l1,
                             cudaFuncAttributeMaxDynamicSharedMemorySize, SMEM_L1);
        attr_done = 1;
    }

    __half *xh, *h1, *h2, *wt;
    cudaGetSymbolAddress((void**)&xh, g_x);
    cudaGetSymbolAddress((void**)&h1, g_h1);
    cudaGetSymbolAddress((void**)&h2, g_h2);
    cudaGetSymbolAddress((void**)&wt, g_Wt);

    // ---- prep: transpose all weights + convert inputs, one launch ----
    PrepArgs pa;
    long long woff[9];
    int tbt = 0;
    {
        long long w = 0;
        for (int t = 0; t < 3; t++) {
            int Ks[3] = {din[t], 512, 512};
            int Ns[3] = {512, 512, 256};
            for (int l = 0; l < 3; l++) {
                int idx = t * 3 + l;
                pa.W[idx] = (const float*)d_in[4 + 6 * t + 2 * l];
                pa.wtoff[idx] = w;
                woff[idx] = w;
                pa.K[idx] = Ks[l];
                pa.N[idx] = Ns[l];
                pa.tbase[idx] = tbt;
                tbt += (Ks[l] / 32) * (Ns[l] / 32);
                w += (long long)Ks[l] * Ns[l];
            }
        }
        pa.tbase[9] = tbt;
        pa.c1 = n[0] * din[0] / 4;
        pa.c2 = pa.c1 + n[1] * din[1] / 4;
        pa.c3 = pa.c2 + n[2] * din[2] / 4;
        for (int t = 0; t < 3; t++) {
            pa.xs[t] = (const float*)d_in[t];
            pa.xd[t] = xh + xoff[t];
        }
        int cvtb = (pa.c3 + 255) / 256;
        prep_kernel<<<tbt + cvtb, 256>>>(pa);
    }

    // ---- layer 1 (full-resident kernel) ----
    {
        L1Args a;
        for (int i = 0; i < 4; i++) a.tb[i] = tb[i];
        for (int t = 0; t < 3; t++) {
            a.A[t] = xh + xoff[t];
            a.C[t] = h1 + hb[t] * 512;
            a.bias[t] = (const float*)d_in[5 + 6 * t];
            a.Wt[t] = wt + woff[t * 3 + 0];
            a.M[t] = n[t];
            a.K[t] = din[t];
        }
        mlp_l1<<<dim3(4, tb[3]), 256, SMEM_L1>>>(a);
    }

    // ---- layers 2 / 3 ----
    LArgs a;
    for (int i = 0; i < 4; i++) a.tb[i] = tb[i];

    a.N = 512;
    for (int t = 0; t < 3; t++) {
        a.A[t] = h1 + hb[t] * 512;
        a.C[t] = h2 + hb[t] * 512;
        a.bias[t] = (const float*)d_in[7 + 6 * t];
        a.Wt[t] = wt + woff[t * 3 + 1];
        a.M[t] = n[t];
        a.K[t] = 512;
    }
    mlp_layer<false><<<dim3(4, tb[3]), 256, SMEM>>>(a);

    a.N = 256;
    for (int t = 0; t < 3; t++) {
        a.A[t] = h2 + hb[t] * 512;
        a.C[t] = (float*)d_out + outbase[t] * 256;
        a.bias[t] = (const float*)d_in[9 + 6 * t];
        a.Wt[t] = wt + woff[t * 3 + 2];
        a.M[t] = n[t];
        a.K[t] = 512;
    }
    mlp_layer<true><<<dim3(2, tb[3]), 256, SMEM>>>(a);
}

// round 15
// speedup vs baseline: 1.6616x; 1.1043x over previous
#include <cuda_runtime.h>
#include <cuda_fp16.h>
#include <cstdint>

// ---------------------------------------------------------------------------
// EncoderByType (GB300, compute_103): fp16 m16n8k16 mma.sync GEMM.
// Round 15: kernels = exact r11 (best: 717.8us). New: per-TYPE stream
// parallelism under graph capture (fork/join with events) so the 3
// independent chains l1(t)->l2(t)->l3(t) overlap; merged prep kernel.
// ---------------------------------------------------------------------------

__device__ __half g_x [32014336];          // padded fp16 inputs
__device__ __half g_h1[240128ll * 512];
__device__ __half g_h2[240128ll * 512];
__device__ __half g_Wt[1409024];           // 9 weights, [N,K] fp16

// ------------------------- helpers -----------------------------------------
__device__ __forceinline__ uint32_t smem_u32(const void* p) {
    uint32_t a;
    asm("{ .reg .u64 t; cvta.to.shared.u64 t, %1; cvt.u32.u64 %0, t; }"
        : "=r"(a) : "l"(p));
    return a;
}
__device__ __forceinline__ float fast_sigmoid(float x) {
    float t;
    asm("tanh.approx.f32 %0, %1;" : "=f"(t) : "f"(0.5f * x));
    return fmaf(0.5f, t, 0.5f);
}
__device__ __forceinline__ uint32_t packh2(float lo, float hi) {
    __half2 h = __floats2half2_rn(lo, hi);
    return *reinterpret_cast<uint32_t*>(&h);
}
__device__ __forceinline__ void mma_fp16(float* d, const uint4& a,
                                         uint32_t b0, uint32_t b1) {
    asm volatile(
        "mma.sync.aligned.m16n8k16.row.col.f32.f16.f16.f32 "
        "{%0,%1,%2,%3}, {%4,%5,%6,%7}, {%8,%9}, {%0,%1,%2,%3};"
        : "+f"(d[0]), "+f"(d[1]), "+f"(d[2]), "+f"(d[3])
        : "r"(a.x), "r"(a.y), "r"(a.z), "r"(a.w), "r"(b0), "r"(b1));
}
__device__ __forceinline__ void ldsm4(uint4& d, uint32_t addr) {
    asm volatile(
        "ldmatrix.sync.aligned.m8n8.x4.shared.b16 {%0,%1,%2,%3}, [%4];"
        : "=r"(d.x), "=r"(d.y), "=r"(d.z), "=r"(d.w) : "r"(addr));
}
#define CP_ASYNC16(dst, src) \
    asm volatile("cp.async.cg.shared.global [%0], [%1], 16;" :: "r"(dst), "l"(src))
#define CP_COMMIT() asm volatile("cp.async.commit_group;" ::: "memory")
#define CP_WAIT(n)  asm volatile("cp.async.wait_group %0;" :: "n"(n) : "memory")

// ------------------------- prep: transpose + cvt in one launch -------------
struct PrepArgs {
    const float* W[9];
    long long wtoff[9];
    int K[9];
    int N[9];
    int tbase[10];
    const float* xs[3];
    __half* xd[3];
    int c1, c2, c3;
};

__global__ void __launch_bounds__(256)
prep_kernel(PrepArgs a) {
    if ((int)blockIdx.x < a.tbase[9]) {
        int m = 0;
        while ((int)blockIdx.x >= a.tbase[m + 1]) m++;
        int t = blockIdx.x - a.tbase[m];
        int Km = a.K[m], Nm = a.N[m];
        int tilesN = Nm >> 5;
        int tk = t / tilesN, tn = t % tilesN;

        __shared__ float tile[32][33];
        int tx = threadIdx.x & 31, ty0 = threadIdx.x >> 5;
        const float* W = a.W[m];
#pragma unroll
        for (int i = 0; i < 4; i++) {
            int ty = ty0 + i * 8;
            tile[ty][tx] = W[(long long)(tk * 32 + ty) * Nm + tn * 32 + tx];
        }
        __syncthreads();
        __half* Wt = g_Wt + a.wtoff[m];
#pragma unroll
        for (int i = 0; i < 4; i++) {
            int ty = ty0 + i * 8;
            Wt[(long long)(tn * 32 + ty) * Km + tk * 32 + tx] = __float2half(tile[tx][ty]);
        }
    } else {
        int i = ((int)blockIdx.x - a.tbase[9]) * 256 + threadIdx.x;
        if (i >= a.c3) return;
        const float* s;
        __half* d;
        int j;
        if (i < a.c1)      { s = a.xs[0]; d = a.xd[0]; j = i; }
        else if (i < a.c2) { s = a.xs[1]; d = a.xd[1]; j = i - a.c1; }
        else               { s = a.xs[2]; d = a.xd[2]; j = i - a.c2; }
        float4 v = ((const float4*)s)[j];
        uint2 o;
        o.x = packh2(v.x, v.y);
        o.y = packh2(v.z, v.w);
        ((uint2*)d)[j] = o;
    }
}

// ------------------------- layer kernel (exact r11) ------------------------
struct LArgs {
    const __half* A;
    void* C;
    const float* bias;
    const __half* Wt;
    int M, K;
    int N;
};

template <bool CF32>
__global__ void __launch_bounds__(256, 2)
mlp_layer(LArgs a)
{
    extern __shared__ char smem[];
    const int K = a.K;
    const int N = a.N;
    const long long bm = (long long)blockIdx.y * 128;
    const int bn = blockIdx.x * 128;
    const __half* Ah = a.A;
    const __half* Wt = a.Wt;
    const int KT = K >> 6;

    const int tid = threadIdx.x;
    const int lane = tid & 31;
    const int wid = tid >> 5;
    const int warp_m = wid & 3;
    const int warp_n = wid >> 2;

    const uint32_t sb = smem_u32(smem);

    const int crow = tid >> 3;
    const int cchk = tid & 7;
    const __half* pA = Ah + (bm + crow) * (long long)K + cchk * 8;
    const __half* pB = Wt + (long long)(bn + crow) * K + cchk * 8;
    const uint32_t swz = (uint32_t)((cchk ^ (crow & 7)) * 16);
    const uint32_t dA = sb + crow * 128 + swz;
    const uint32_t dB = sb + 16384 + crow * 128 + swz;
    const long long rstep = 32ll * K;

    const int l15 = lane & 15;
    const int ahi = lane >> 4;
    const uint32_t aX = (uint32_t)(lane & 7);
    const uint32_t aBase = sb + (uint32_t)(warp_m * 32 + l15) * 128;
    const int bn_l = warp_n * 64 + ((lane >> 4) << 3) + (lane & 7);
    const int bhi = (lane >> 3) & 1;
    const uint32_t bBase = sb + 16384 + (uint32_t)bn_l * 128;

    float acc[2][8][4];
#pragma unroll
    for (int i = 0; i < 2; i++)
#pragma unroll
        for (int j = 0; j < 8; j++)
#pragma unroll
            for (int q = 0; q < 4; q++) acc[i][j][q] = 0.0f;

#define ISSUE(kt, slot)                                                      \
    do {                                                                     \
        const __half* sA_ = pA + (kt) * 64;                                  \
        const __half* sB_ = pB + (kt) * 64;                                  \
        uint32_t oA_ = dA + (slot) * 32768u;                                 \
        uint32_t oB_ = dB + (slot) * 32768u;                                 \
        _Pragma("unroll")                                                    \
        for (int i = 0; i < 4; i++)                                          \
            CP_ASYNC16(oA_ + i * 4096u, sA_ + i * rstep);                    \
        _Pragma("unroll")                                                    \
        for (int i = 0; i < 4; i++)                                          \
            CP_ASYNC16(oB_ + i * 4096u, sB_ + i * rstep);                    \
    } while (0)

    ISSUE(0, 0);
    CP_COMMIT();
    if (1 < KT) ISSUE(1, 1);
    CP_COMMIT();

    int pf = 2;
    for (int kt = 0; kt < KT; kt++) {
        CP_WAIT(1);
        __syncthreads();
        if (pf < KT) {
            int slot = pf - (pf / 3) * 3;
            ISSUE(pf, slot);
        }
        CP_COMMIT();
        pf++;

        const int cur = kt - (kt / 3) * 3;
        const uint32_t aS = aBase + cur * 32768u;
        const uint32_t bS = bBase + cur * 32768u;
#pragma unroll
        for (int s = 0; s < 4; s++) {
            uint4 af[2];
#pragma unroll
            for (int mt = 0; mt < 2; mt++)
                ldsm4(af[mt], aS + mt * 2048u + ((((uint32_t)(2 * s + ahi)) ^ aX) << 4));
            uint4 bf[4];
#pragma unroll
            for (int ng = 0; ng < 4; ng++)
                ldsm4(bf[ng], bS + ng * 2048u + ((((uint32_t)(2 * s + bhi)) ^ aX) << 4));
#pragma unroll
            for (int mt = 0; mt < 2; mt++)
#pragma unroll
                for (int ng = 0; ng < 4; ng++) {
                    mma_fp16(acc[mt][2 * ng],     af[mt], bf[ng].x, bf[ng].y);
                    mma_fp16(acc[mt][2 * ng + 1], af[mt], bf[ng].z, bf[ng].w);
                }
        }
    }
#undef ISSUE

    const float* bias = a.bias;
    const int M = a.M;
#pragma unroll
    for (int mt = 0; mt < 2; mt++) {
        long long r0 = bm + warp_m * 32 + mt * 16 + (lane >> 2);
        long long r1 = r0 + 8;
#pragma unroll
        for (int np = 0; np < 8; np++) {
            int n = bn + warp_n * 64 + np * 8 + 2 * (lane & 3);
            float2 bv = *(const float2*)(bias + n);
            float* d = acc[mt][np];
            float s0 = fast_sigmoid(d[0] + bv.x);
            float s1 = fast_sigmoid(d[1] + bv.y);
            float s2 = fast_sigmoid(d[2] + bv.x);
            float s3 = fast_sigmoid(d[3] + bv.y);
            if (CF32) {
                float* C = (float*)a.C;
                if (r0 < M) *(float2*)(C + r0 * N + n) = make_float2(s0, s1);
                if (r1 < M) *(float2*)(C + r1 * N + n) = make_float2(s2, s3);
            } else {
                __half* C = (__half*)a.C;
                *(uint32_t*)(C + r0 * N + n) = packh2(s0, s1);
                *(uint32_t*)(C + r1 * N + n) = packh2(s2, s3);
            }
        }
    }
}

// ------------------------- host launcher -----------------------------------
extern "C" void kernel_launch(void* const* d_in, const int* in_sizes, int n_in,
                              void* d_out, int out_size)
{
    (void)n_in; (void)out_size;
    const int din[3] = {64, 128, 256};
    int n[3];
    for (int t = 0; t < 3; t++) n[t] = in_sizes[t] / din[t];

    int tiles[3];
    for (int t = 0; t < 3; t++) tiles[t] = (n[t] + 127) / 128;
    long long padrows[3] = {(long long)tiles[0] * 128, (long long)tiles[1] * 128,
                            (long long)tiles[2] * 128};
    long long hb[3] = {0, padrows[0], padrows[0] + padrows[1]};
    long long xoff[3] = {0, padrows[0] * din[0],
                         padrows[0] * din[0] + padrows[1] * din[1]};
    long long outbase[3] = {0, n[0], (long long)n[0] + n[1]};

    const int SMEM = 3 * 32768;
    static cudaStream_t st[3] = {nullptr, nullptr, nullptr};
    static cudaEvent_t evP = nullptr, evJ1 = nullptr, evJ2 = nullptr;
    if (!st[1]) {
        cudaFuncSetAttribute(mlp_layer<false>,
                             cudaFuncAttributeMaxDynamicSharedMemorySize, SMEM);
        cudaFuncSetAttribute(mlp_layer<true>,
                             cudaFuncAttributeMaxDynamicSharedMemorySize, SMEM);
        st[0] = 0;   // capture/default stream for type 0
        cudaStreamCreateWithFlags(&st[1], cudaStreamNonBlocking);
        cudaStreamCreateWithFlags(&st[2], cudaStreamNonBlocking);
        cudaEventCreateWithFlags(&evP, cudaEventDisableTiming);
        cudaEventCreateWithFlags(&evJ1, cudaEventDisableTiming);
        cudaEventCreateWithFlags(&evJ2, cudaEventDisableTiming);
    }

    __half *xh, *h1, *h2, *wt;
    cudaGetSymbolAddress((void**)&xh, g_x);
    cudaGetSymbolAddress((void**)&h1, g_h1);
    cudaGetSymbolAddress((void**)&h2, g_h2);
    cudaGetSymbolAddress((void**)&wt, g_Wt);

    // ---- prep: transpose weights + convert inputs (default stream) ----
    PrepArgs pa;
    long long woff[9];
    {
        long long w = 0;
        int tbt = 0;
        for (int t = 0; t < 3; t++) {
            int Ks[3] = {din[t], 512, 512};
            int Ns[3] = {512, 512, 256};
            for (int l = 0; l < 3; l++) {
                int idx = t * 3 + l;
                pa.W[idx] = (const float*)d_in[4 + 6 * t + 2 * l];
                pa.wtoff[idx] = w;
                woff[idx] = w;
                pa.K[idx] = Ks[l];
                pa.N[idx] = Ns[l];
                pa.tbase[idx] = tbt;
                tbt += (Ks[l] / 32) * (Ns[l] / 32);
                w += (long long)Ks[l] * Ns[l];
            }
        }
        pa.tbase[9] = tbt;
        pa.c1 = n[0] * din[0] / 4;
        pa.c2 = pa.c1 + n[1] * din[1] / 4;
        pa.c3 = pa.c2 + n[2] * din[2] / 4;
        for (int t = 0; t < 3; t++) {
            pa.xs[t] = (const float*)d_in[t];
            pa.xd[t] = xh + xoff[t];
        }
        int cvtb = (pa.c3 + 255) / 256;
        prep_kernel<<<tbt + cvtb, 256>>>(pa);
    }

    // ---- fork: types 1,2 onto side streams after prep ----
    cudaEventRecord(evP, st[0]);
    cudaStreamWaitEvent(st[1], evP, 0);
    cudaStreamWaitEvent(st[2], evP, 0);

    // ---- per-type chains l1 -> l2 -> l3 ----
    for (int t = 0; t < 3; t++) {
        cudaStream_t s = st[t];
        LArgs a;
        a.M = n[t];
        // layer 1
        a.A = xh + xoff[t];
        a.C = h1 + hb[t] * 512;
        a.bias = (const float*)d_in[5 + 6 * t];
        a.Wt = wt + woff[t * 3 + 0];
        a.K = din[t];
        a.N = 512;
        mlp_layer<false><<<dim3(4, tiles[t]), 256, SMEM, s>>>(a);
        // layer 2
        a.A = h1 + hb[t] * 512;
        a.C = h2 + hb[t] * 512;
        a.bias = (const float*)d_in[7 + 6 * t];
        a.Wt = wt + woff[t * 3 + 1];
        a.K = 512;
        a.N = 512;
        mlp_layer<false><<<dim3(4, tiles[t]), 256, SMEM, s>>>(a);
        // layer 3
        a.A = h2 + hb[t] * 512;
        a.C = (float*)d_out + outbase[t] * 256;
        a.bias = (const float*)d_in[9 + 6 * t];
        a.Wt = wt + woff[t * 3 + 2];
        a.K = 512;
        a.N = 256;
        mlp_layer<true><<<dim3(2, tiles[t]), 256, SMEM, s>>>(a);
    }

    // ---- join side streams back into the capture stream ----
    cudaEventRecord(evJ1, st[1]);
    cudaEventRecord(evJ2, st[2]);
    cudaStreamWaitEvent(st[0], evJ1, 0);
    cudaStreamWaitEvent(st[0], evJ2, 0);
}

// round 16
// speedup vs baseline: 1.7416x; 1.0481x over previous
#include <cuda_runtime.h>
#include <cuda_fp16.h>
#include <cstdint>

// ---------------------------------------------------------------------------
// EncoderByType (GB300, compute_103): fp16 m16n8k16 mma.sync GEMM.
// Round 16: l2/l3 = exact r11 merged kernels (best known). Layer 1 replaced
// by B-RESIDENT MULTI-TILE kernel: weights staged once per CTA, grid-stride
// over m-tiles with 2-slot A ring (barriers per tile, not per kt).
// ---------------------------------------------------------------------------

__device__ __half g_x [32014336];          // padded fp16 inputs (zero-init)
__device__ __half g_h1[240128ll * 512];
__device__ __half g_h2[240128ll * 512];
__device__ __half g_Wt[1409024];           // 9 weights, [N,K] fp16

// ------------------------- helpers -----------------------------------------
__device__ __forceinline__ uint32_t smem_u32(const void* p) {
    uint32_t a;
    asm("{ .reg .u64 t; cvta.to.shared.u64 t, %1; cvt.u32.u64 %0, t; }"
        : "=r"(a) : "l"(p));
    return a;
}
__device__ __forceinline__ float fast_sigmoid(float x) {
    float t;
    asm("tanh.approx.f32 %0, %1;" : "=f"(t) : "f"(0.5f * x));
    return fmaf(0.5f, t, 0.5f);
}
__device__ __forceinline__ uint32_t packh2(float lo, float hi) {
    __half2 h = __floats2half2_rn(lo, hi);
    return *reinterpret_cast<uint32_t*>(&h);
}
__device__ __forceinline__ void mma_fp16(float* d, const uint4& a,
                                         uint32_t b0, uint32_t b1) {
    asm volatile(
        "mma.sync.aligned.m16n8k16.row.col.f32.f16.f16.f32 "
        "{%0,%1,%2,%3}, {%4,%5,%6,%7}, {%8,%9}, {%0,%1,%2,%3};"
        : "+f"(d[0]), "+f"(d[1]), "+f"(d[2]), "+f"(d[3])
        : "r"(a.x), "r"(a.y), "r"(a.z), "r"(a.w), "r"(b0), "r"(b1));
}
__device__ __forceinline__ void ldsm4(uint4& d, uint32_t addr) {
    asm volatile(
        "ldmatrix.sync.aligned.m8n8.x4.shared.b16 {%0,%1,%2,%3}, [%4];"
        : "=r"(d.x), "=r"(d.y), "=r"(d.z), "=r"(d.w) : "r"(addr));
}
#define CP_ASYNC16(dst, src) \
    asm volatile("cp.async.cg.shared.global [%0], [%1], 16;" :: "r"(dst), "l"(src))
#define CP_COMMIT() asm volatile("cp.async.commit_group;" ::: "memory")
#define CP_WAIT(n)  asm volatile("cp.async.wait_group %0;" :: "n"(n) : "memory")

// ------------------------- prep: transpose + cvt in one launch -------------
struct PrepArgs {
    const float* W[9];
    long long wtoff[9];
    int K[9];
    int N[9];
    int tbase[10];
    const float* xs[3];
    __half* xd[3];
    int c1, c2, c3;
};

__global__ void __launch_bounds__(256)
prep_kernel(PrepArgs a) {
    if ((int)blockIdx.x < a.tbase[9]) {
        int m = 0;
        while ((int)blockIdx.x >= a.tbase[m + 1]) m++;
        int t = blockIdx.x - a.tbase[m];
        int Km = a.K[m], Nm = a.N[m];
        int tilesN = Nm >> 5;
        int tk = t / tilesN, tn = t % tilesN;

        __shared__ float tile[32][33];
        int tx = threadIdx.x & 31, ty0 = threadIdx.x >> 5;
        const float* W = a.W[m];
#pragma unroll
        for (int i = 0; i < 4; i++) {
            int ty = ty0 + i * 8;
            tile[ty][tx] = W[(long long)(tk * 32 + ty) * Nm + tn * 32 + tx];
        }
        __syncthreads();
        __half* Wt = g_Wt + a.wtoff[m];
#pragma unroll
        for (int i = 0; i < 4; i++) {
            int ty = ty0 + i * 8;
            Wt[(long long)(tn * 32 + ty) * Km + tk * 32 + tx] = __float2half(tile[tx][ty]);
        }
    } else {
        int i = ((int)blockIdx.x - a.tbase[9]) * 256 + threadIdx.x;
        if (i >= a.c3) return;
        const float* s;
        __half* d;
        int j;
        if (i < a.c1)      { s = a.xs[0]; d = a.xd[0]; j = i; }
        else if (i < a.c2) { s = a.xs[1]; d = a.xd[1]; j = i - a.c1; }
        else               { s = a.xs[2]; d = a.xd[2]; j = i - a.c2; }
        float4 v = ((const float4*)s)[j];
        uint2 o;
        o.x = packh2(v.x, v.y);
        o.y = packh2(v.z, v.w);
        ((uint2*)d)[j] = o;
    }
}

// ------------------------- layer-1: B-resident multi-tile ------------------
// Grid (4, min(tiles, gy)). 256 thr = 8 warps (4m x 2n), warp 32x64, N=512.
// Smem: B resident (256*K bytes) + 2 A slots (256*K each). Grid-stride over
// m-tiles; A(i+2) staged while tile i computes; barriers 2 per tile.
template <int KV>
__global__ void __launch_bounds__(256, 2)
mlp_l1(const __half* __restrict__ A, __half* __restrict__ C,
       const float* __restrict__ bias, const __half* __restrict__ Wt,
       int M, int tiles)
{
    constexpr int KT = KV >> 6;
    constexpr int CPR = KV >> 3;                 // 16B chunks per row
    constexpr int LG = (KV == 64) ? 3 : (KV == 128 ? 4 : 5);
    constexpr uint32_t TILE_B = 256u * KV;       // bytes per 128-row tile

    extern __shared__ char smem[];
    const int bn = blockIdx.x * 128;
    const int tid = threadIdx.x, lane = tid & 31, wid = tid >> 5;
    const int warp_m = wid & 3, warp_n = wid >> 2;
    const uint32_t sb = smem_u32(smem);
    const uint32_t bufB = sb;
    const uint32_t bufA0 = sb + TILE_B;
    const uint32_t bufA1 = sb + 2 * TILE_B;

    // ---- stage resident B ----
#pragma unroll
    for (int it = 0; it < CPR / 2; it++) {
        int idx = tid + it * 256;
        int row = idx >> LG, ck = idx & (CPR - 1);
        int phys = (ck & ~7) | ((ck ^ row) & 7);
        uint32_t off = (uint32_t)(idx - ck + phys) << 4;
        CP_ASYNC16(bufB + off, Wt + (long long)(bn + row) * KV + ck * 8);
    }

    const int mt0 = blockIdx.y;
    const int gy = gridDim.y;

#define STAGE_A(mt_, dst_)                                                    \
    do {                                                                      \
        const __half* src_ = A + (long long)(mt_) * 128 * KV;                 \
        _Pragma("unroll")                                                     \
        for (int it = 0; it < CPR / 2; it++) {                                \
            int idx = tid + it * 256;                                         \
            int row = idx >> LG, ck = idx & (CPR - 1);                        \
            int phys = (ck & ~7) | ((ck ^ row) & 7);                          \
            uint32_t off = (uint32_t)(idx - ck + phys) << 4;                  \
            CP_ASYNC16((dst_) + off, src_ + (long long)row * KV + ck * 8);    \
        }                                                                     \
    } while (0)

    STAGE_A(mt0, bufA0);          // group0 = B + A(tile0)
    CP_COMMIT();
    if (mt0 + gy < tiles) STAGE_A(mt0 + gy, bufA1);
    CP_COMMIT();                  // group1 = A(tile1) (possibly empty)

    // ---- fragment addressing ----
    const int l15 = lane & 15;
    const int ahi = lane >> 4;
    const int lx = lane & 7;
    const int brow_l = ((lane >> 4) << 3) + lx;
    const int bhi = (lane >> 3) & 1;
    const uint32_t bR = bufB + (uint32_t)(warp_n * 64 + brow_l) * (KV * 2);
    const uint32_t aRowOff = (uint32_t)(warp_m * 32 + l15) * (KV * 2);

    int i = 0;
    for (int mt = mt0; mt < tiles; mt += gy, i++) {
        CP_WAIT(1);
        __syncthreads();

        float acc[2][8][4];
#pragma unroll
        for (int q1 = 0; q1 < 2; q1++)
#pragma unroll
            for (int q2 = 0; q2 < 8; q2++)
#pragma unroll
                for (int q3 = 0; q3 < 4; q3++) acc[q1][q2][q3] = 0.0f;

        const uint32_t aR = ((i & 1) ? bufA1 : bufA0) + aRowOff;
#pragma unroll
        for (int kt = 0; kt < KT; kt++)
#pragma unroll
            for (int s = 0; s < 4; s++) {
                const int cka = kt * 8 + 2 * s + ahi;
                const int ckb = kt * 8 + 2 * s + bhi;
                const uint32_t pa = (uint32_t)((cka & ~7) | ((cka ^ lx) & 7)) << 4;
                const uint32_t pb = (uint32_t)((ckb & ~7) | ((ckb ^ lx) & 7)) << 4;
                uint4 af[2], bf[4];
#pragma unroll
                for (int mt2 = 0; mt2 < 2; mt2++)
                    ldsm4(af[mt2], aR + (uint32_t)(mt2 * 16) * (KV * 2) + pa);
#pragma unroll
                for (int ng = 0; ng < 4; ng++)
                    ldsm4(bf[ng], bR + (uint32_t)(ng * 16) * (KV * 2) + pb);
#pragma unroll
                for (int mt2 = 0; mt2 < 2; mt2++)
#pragma unroll
                    for (int ng = 0; ng < 4; ng++) {
                        mma_fp16(acc[mt2][2 * ng],     af[mt2], bf[ng].x, bf[ng].y);
                        mma_fp16(acc[mt2][2 * ng + 1], af[mt2], bf[ng].z, bf[ng].w);
                    }
            }

        // ---- epilogue: bias + sigmoid -> fp16 (N = 512) ----
#pragma unroll
        for (int mt2 = 0; mt2 < 2; mt2++) {
            long long r0 = (long long)mt * 128 + warp_m * 32 + mt2 * 16 + (lane >> 2);
            long long r1 = r0 + 8;
#pragma unroll
            for (int np = 0; np < 8; np++) {
                int n = bn + warp_n * 64 + np * 8 + 2 * (lane & 3);
                float2 bv = *(const float2*)(bias + n);
                float* d = acc[mt2][np];
                if (r0 < M)
                    *(uint32_t*)(C + r0 * 512 + n) =
                        packh2(fast_sigmoid(d[0] + bv.x), fast_sigmoid(d[1] + bv.y));
                if (r1 < M)
                    *(uint32_t*)(C + r1 * 512 + n) =
                        packh2(fast_sigmoid(d[2] + bv.x), fast_sigmoid(d[3] + bv.y));
            }
        }

        __syncthreads();   // all reads of this A slot done before re-staging
        if (mt + 2 * gy < tiles)
            STAGE_A(mt + 2 * gy, (i & 1) ? bufA1 : bufA0);
        CP_COMMIT();
    }
#undef STAGE_A
}

// ------------------------- layers 2/3 kernel (exact r11) -------------------
struct LArgs {
    const __half* A[3];
    void* C[3];
    const float* bias[3];
    const __half* Wt[3];
    int M[3], K[3];
    int tb[4];
    int N;
};

template <bool CF32>
__global__ void __launch_bounds__(256, 2)
mlp_layer(LArgs a)
{
    extern __shared__ char smem[];
    const int t = ((int)blockIdx.y >= a.tb[1]) + ((int)blockIdx.y >= a.tb[2]);
    const int K = a.K[t];
    const int N = a.N;
    const long long bm = (long long)((int)blockIdx.y - a.tb[t]) * 128;
    const int bn = blockIdx.x * 128;
    const __half* Ah = a.A[t];
    const __half* Wt = a.Wt[t];
    const int KT = K >> 6;

    const int tid = threadIdx.x;
    const int lane = tid & 31;
    const int wid = tid >> 5;
    const int warp_m = wid & 3;
    const int warp_n = wid >> 2;

    const uint32_t sb = smem_u32(smem);

    const int crow = tid >> 3;
    const int cchk = tid & 7;
    const __half* pA = Ah + (bm + crow) * (long long)K + cchk * 8;
    const __half* pB = Wt + (long long)(bn + crow) * K + cchk * 8;
    const uint32_t swz = (uint32_t)((cchk ^ (crow & 7)) * 16);
    const uint32_t dA = sb + crow * 128 + swz;
    const uint32_t dB = sb + 16384 + crow * 128 + swz;
    const long long rstep = 32ll * K;

    const int l15 = lane & 15;
    const int ahi = lane >> 4;
    const uint32_t aX = (uint32_t)(lane & 7);
    const uint32_t aBase = sb + (uint32_t)(warp_m * 32 + l15) * 128;
    const int bn_l = warp_n * 64 + ((lane >> 4) << 3) + (lane & 7);
    const int bhi = (lane >> 3) & 1;
    const uint32_t bBase = sb + 16384 + (uint32_t)bn_l * 128;

    float acc[2][8][4];
#pragma unroll
    for (int i = 0; i < 2; i++)
#pragma unroll
        for (int j = 0; j < 8; j++)
#pragma unroll
            for (int q = 0; q < 4; q++) acc[i][j][q] = 0.0f;

#define ISSUE(kt, slot)                                                      \
    do {                                                                     \
        const __half* sA_ = pA + (kt) * 64;                                  \
        const __half* sB_ = pB + (kt) * 64;                                  \
        uint32_t oA_ = dA + (slot) * 32768u;                                 \
        uint32_t oB_ = dB + (slot) * 32768u;                                 \
        _Pragma("unroll")                                                    \
        for (int i = 0; i < 4; i++)                                          \
            CP_ASYNC16(oA_ + i * 4096u, sA_ + i * rstep);                    \
        _Pragma("unroll")                                                    \
        for (int i = 0; i < 4; i++)                                          \
            CP_ASYNC16(oB_ + i * 4096u, sB_ + i * rstep);                    \
    } while (0)

    ISSUE(0, 0);
    CP_COMMIT();
    if (1 < KT) ISSUE(1, 1);
    CP_COMMIT();

    int pf = 2;
    for (int kt = 0; kt < KT; kt++) {
        CP_WAIT(1);
        __syncthreads();
        if (pf < KT) {
            int slot = pf - (pf / 3) * 3;
            ISSUE(pf, slot);
        }
        CP_COMMIT();
        pf++;

        const int cur = kt - (kt / 3) * 3;
        const uint32_t aS = aBase + cur * 32768u;
        const uint32_t bS = bBase + cur * 32768u;
#pragma unroll
        for (int s = 0; s < 4; s++) {
            uint4 af[2];
#pragma unroll
            for (int mt = 0; mt < 2; mt++)
                ldsm4(af[mt], aS + mt * 2048u + ((((uint32_t)(2 * s + ahi)) ^ aX) << 4));
            uint4 bf[4];
#pragma unroll
            for (int ng = 0; ng < 4; ng++)
                ldsm4(bf[ng], bS + ng * 2048u + ((((uint32_t)(2 * s + bhi)) ^ aX) << 4));
#pragma unroll
            for (int mt = 0; mt < 2; mt++)
#pragma unroll
                for (int ng = 0; ng < 4; ng++) {
                    mma_fp16(acc[mt][2 * ng],     af[mt], bf[ng].x, bf[ng].y);
                    mma_fp16(acc[mt][2 * ng + 1], af[mt], bf[ng].z, bf[ng].w);
                }
        }
    }
#undef ISSUE

    const float* bias = a.bias[t];
    const int M = a.M[t];
#pragma unroll
    for (int mt = 0; mt < 2; mt++) {
        long long r0 = bm + warp_m * 32 + mt * 16 + (lane >> 2);
        long long r1 = r0 + 8;
#pragma unroll
        for (int np = 0; np < 8; np++) {
            int n = bn + warp_n * 64 + np * 8 + 2 * (lane & 3);
            float2 bv = *(const float2*)(bias + n);
            float* d = acc[mt][np];
            float s0 = fast_sigmoid(d[0] + bv.x);
            float s1 = fast_sigmoid(d[1] + bv.y);
            float s2 = fast_sigmoid(d[2] + bv.x);
            float s3 = fast_sigmoid(d[3] + bv.y);
            if (CF32) {
                float* C = (float*)a.C[t];
                if (r0 < M) *(float2*)(C + r0 * N + n) = make_float2(s0, s1);
                if (r1 < M) *(float2*)(C + r1 * N + n) = make_float2(s2, s3);
            } else {
                __half* C = (__half*)a.C[t];
                *(uint32_t*)(C + r0 * N + n) = packh2(s0, s1);
                *(uint32_t*)(C + r1 * N + n) = packh2(s2, s3);
            }
        }
    }
}

// ------------------------- host launcher -----------------------------------
extern "C" void kernel_launch(void* const* d_in, const int* in_sizes, int n_in,
                              void* d_out, int out_size)
{
    (void)n_in; (void)out_size;
    const int din[3] = {64, 128, 256};
    int n[3];
    for (int t = 0; t < 3; t++) n[t] = in_sizes[t] / din[t];

    int tiles[3], tb[4];
    tb[0] = 0;
    for (int t = 0; t < 3; t++) {
        tiles[t] = (n[t] + 127) / 128;
        tb[t + 1] = tb[t] + tiles[t];
    }
    long long padrows[3] = {(long long)tiles[0] * 128, (long long)tiles[1] * 128,
                            (long long)tiles[2] * 128};
    long long hb[3] = {0, padrows[0], padrows[0] + padrows[1]};
    long long xoff[3] = {0, padrows[0] * din[0],
                         padrows[0] * din[0] + padrows[1] * din[1]};
    long long outbase[3] = {0, n[0], (long long)n[0] + n[1]};

    const int SMEM = 3 * 32768;
    static int attr_done = 0;
    if (!attr_done) {
        cudaFuncSetAttribute(mlp_layer<false>,
                             cudaFuncAttributeMaxDynamicSharedMemorySize, SMEM);
        cudaFuncSetAttribute(mlp_layer<true>,
                             cudaFuncAttributeMaxDynamicSharedMemorySize, SMEM);
        cudaFuncSetAttribute(mlp_l1<64>,
                             cudaFuncAttributeMaxDynamicSharedMemorySize, 3 * 256 * 64);
        cudaFuncSetAttribute(mlp_l1<128>,
                             cudaFuncAttributeMaxDynamicSharedMemorySize, 3 * 256 * 128);
        cudaFuncSetAttribute(mlp_l1<256>,
                             cudaFuncAttributeMaxDynamicSharedMemorySize, 3 * 256 * 256);
        attr_done = 1;
    }

    __half *xh, *h1, *h2, *wt;
    cudaGetSymbolAddress((void**)&xh, g_x);
    cudaGetSymbolAddress((void**)&h1, g_h1);
    cudaGetSymbolAddress((void**)&h2, g_h2);
    cudaGetSymbolAddress((void**)&wt, g_Wt);

    // ---- prep: transpose weights + convert inputs ----
    PrepArgs pa;
    long long woff[9];
    {
        long long w = 0;
        int tbt = 0;
        for (int t = 0; t < 3; t++) {
            int Ks[3] = {din[t], 512, 512};
            int Ns[3] = {512, 512, 256};
            for (int l = 0; l < 3; l++) {
                int idx = t * 3 + l;
                pa.W[idx] = (const float*)d_in[4 + 6 * t + 2 * l];
                pa.wtoff[idx] = w;
                woff[idx] = w;
                pa.K[idx] = Ks[l];
                pa.N[idx] = Ns[l];
                pa.tbase[idx] = tbt;
                tbt += (Ks[l] / 32) * (Ns[l] / 32);
                w += (long long)Ks[l] * Ns[l];
            }
        }
        pa.tbase[9] = tbt;
        pa.c1 = n[0] * din[0] / 4;
        pa.c2 = pa.c1 + n[1] * din[1] / 4;
        pa.c3 = pa.c2 + n[2] * din[2] / 4;
        for (int t = 0; t < 3; t++) {
            pa.xs[t] = (const float*)d_in[t];
            pa.xd[t] = xh + xoff[t];
        }
        int cvtb = (pa.c3 + 255) / 256;
        prep_kernel<<<tbt + cvtb, 256>>>(pa);
    }

    // ---- layer 1: B-resident multi-tile, one launch per type ----
    {
        int gy0 = tiles[0] < 74 ? tiles[0] : 74;
        int gy1 = tiles[1] < 74 ? tiles[1] : 74;
        int gy2 = tiles[2] < 37 ? tiles[2] : 37;
        mlp_l1<64><<<dim3(4, gy0), 256, 3 * 256 * 64>>>(
            xh + xoff[0], h1 + hb[0] * 512, (const float*)d_in[5],
            wt + woff[0], n[0], tiles[0]);
        mlp_l1<128><<<dim3(4, gy1), 256, 3 * 256 * 128>>>(
            xh + xoff[1], h1 + hb[1] * 512, (const float*)d_in[11],
            wt + woff[3], n[1], tiles[1]);
        mlp_l1<256><<<dim3(4, gy2), 256, 3 * 256 * 256>>>(
            xh + xoff[2], h1 + hb[2] * 512, (const float*)d_in[17],
            wt + woff[6], n[2], tiles[2]);
    }

    // ---- layers 2 / 3 (merged, exact r11) ----
    LArgs a;
    for (int i = 0; i < 4; i++) a.tb[i] = tb[i];

    a.N = 512;
    for (int t = 0; t < 3; t++) {
        a.A[t] = h1 + hb[t] * 512;
        a.C[t] = h2 + hb[t] * 512;
        a.bias[t] = (const float*)d_in[7 + 6 * t];
        a.Wt[t] = wt + woff[t * 3 + 1];
        a.M[t] = n[t];
        a.K[t] = 512;
    }
    mlp_layer<false><<<dim3(4, tb[3]), 256, SMEM>>>(a);

    a.N = 256;
    for (int t = 0; t < 3; t++) {
        a.A[t] = h2 + hb[t] * 512;
        a.C[t] = (float*)d_out + outbase[t] * 256;
        a.bias[t] = (const float*)d_in[9 + 6 * t];
        a.Wt[t] = wt + woff[t * 3 + 2];
        a.M[t] = n[t];
        a.K[t] = 512;
    }
    mlp_layer<true><<<dim3(2, tb[3]), 256, SMEM>>>(a);
}

// round 17
// speedup vs baseline: 1.7564x; 1.0085x over previous
#include <cuda_runtime.h>
#include <cuda_fp16.h>
#include <cstdint>

// ---------------------------------------------------------------------------
// EncoderByType (GB300, compute_103): fp16 m16n8k16 mma.sync GEMM.
// Round 17: r16 structure (B-resident multi-tile l1, r11 l2/l3) + the three
// one-wave l1 launches run CONCURRENTLY on forked streams (fork after prep,
// join before l2). Kernels byte-identical to r16.
// ---------------------------------------------------------------------------

__device__ __half g_x [32014336];          // padded fp16 inputs (zero-init)
__device__ __half g_h1[240128ll * 512];
__device__ __half g_h2[240128ll * 512];
__device__ __half g_Wt[1409024];           // 9 weights, [N,K] fp16

// ------------------------- helpers -----------------------------------------
__device__ __forceinline__ uint32_t smem_u32(const void* p) {
    uint32_t a;
    asm("{ .reg .u64 t; cvta.to.shared.u64 t, %1; cvt.u32.u64 %0, t; }"
        : "=r"(a) : "l"(p));
    return a;
}
__device__ __forceinline__ float fast_sigmoid(float x) {
    float t;
    asm("tanh.approx.f32 %0, %1;" : "=f"(t) : "f"(0.5f * x));
    return fmaf(0.5f, t, 0.5f);
}
__device__ __forceinline__ uint32_t packh2(float lo, float hi) {
    __half2 h = __floats2half2_rn(lo, hi);
    return *reinterpret_cast<uint32_t*>(&h);
}
__device__ __forceinline__ void mma_fp16(float* d, const uint4& a,
                                         uint32_t b0, uint32_t b1) {
    asm volatile(
        "mma.sync.aligned.m16n8k16.row.col.f32.f16.f16.f32 "
        "{%0,%1,%2,%3}, {%4,%5,%6,%7}, {%8,%9}, {%0,%1,%2,%3};"
        : "+f"(d[0]), "+f"(d[1]), "+f"(d[2]), "+f"(d[3])
        : "r"(a.x), "r"(a.y), "r"(a.z), "r"(a.w), "r"(b0), "r"(b1));
}
__device__ __forceinline__ void ldsm4(uint4& d, uint32_t addr) {
    asm volatile(
        "ldmatrix.sync.aligned.m8n8.x4.shared.b16 {%0,%1,%2,%3}, [%4];"
        : "=r"(d.x), "=r"(d.y), "=r"(d.z), "=r"(d.w) : "r"(addr));
}
#define CP_ASYNC16(dst, src) \
    asm volatile("cp.async.cg.shared.global [%0], [%1], 16;" :: "r"(dst), "l"(src))
#define CP_COMMIT() asm volatile("cp.async.commit_group;" ::: "memory")
#define CP_WAIT(n)  asm volatile("cp.async.wait_group %0;" :: "n"(n) : "memory")

// ------------------------- prep: transpose + cvt in one launch -------------
struct PrepArgs {
    const float* W[9];
    long long wtoff[9];
    int K[9];
    int N[9];
    int tbase[10];
    const float* xs[3];
    __half* xd[3];
    int c1, c2, c3;
};

__global__ void __launch_bounds__(256)
prep_kernel(PrepArgs a) {
    if ((int)blockIdx.x < a.tbase[9]) {
        int m = 0;
        while ((int)blockIdx.x >= a.tbase[m + 1]) m++;
        int t = blockIdx.x - a.tbase[m];
        int Km = a.K[m], Nm = a.N[m];
        int tilesN = Nm >> 5;
        int tk = t / tilesN, tn = t % tilesN;

        __shared__ float tile[32][33];
        int tx = threadIdx.x & 31, ty0 = threadIdx.x >> 5;
        const float* W = a.W[m];
#pragma unroll
        for (int i = 0; i < 4; i++) {
            int ty = ty0 + i * 8;
            tile[ty][tx] = W[(long long)(tk * 32 + ty) * Nm + tn * 32 + tx];
        }
        __syncthreads();
        __half* Wt = g_Wt + a.wtoff[m];
#pragma unroll
        for (int i = 0; i < 4; i++) {
            int ty = ty0 + i * 8;
            Wt[(long long)(tn * 32 + ty) * Km + tk * 32 + tx] = __float2half(tile[tx][ty]);
        }
    } else {
        int i = ((int)blockIdx.x - a.tbase[9]) * 256 + threadIdx.x;
        if (i >= a.c3) return;
        const float* s;
        __half* d;
        int j;
        if (i < a.c1)      { s = a.xs[0]; d = a.xd[0]; j = i; }
        else if (i < a.c2) { s = a.xs[1]; d = a.xd[1]; j = i - a.c1; }
        else               { s = a.xs[2]; d = a.xd[2]; j = i - a.c2; }
        float4 v = ((const float4*)s)[j];
        uint2 o;
        o.x = packh2(v.x, v.y);
        o.y = packh2(v.z, v.w);
        ((uint2*)d)[j] = o;
    }
}

// ------------------------- layer-1: B-resident multi-tile ------------------
template <int KV>
__global__ void __launch_bounds__(256, 2)
mlp_l1(const __half* __restrict__ A, __half* __restrict__ C,
       const float* __restrict__ bias, const __half* __restrict__ Wt,
       int M, int tiles)
{
    constexpr int KT = KV >> 6;
    constexpr int CPR = KV >> 3;
    constexpr int LG = (KV == 64) ? 3 : (KV == 128 ? 4 : 5);
    constexpr uint32_t TILE_B = 256u * KV;

    extern __shared__ char smem[];
    const int bn = blockIdx.x * 128;
    const int tid = threadIdx.x, lane = tid & 31, wid = tid >> 5;
    const int warp_m = wid & 3, warp_n = wid >> 2;
    const uint32_t sb = smem_u32(smem);
    const uint32_t bufB = sb;
    const uint32_t bufA0 = sb + TILE_B;
    const uint32_t bufA1 = sb + 2 * TILE_B;

    // ---- stage resident B ----
#pragma unroll
    for (int it = 0; it < CPR / 2; it++) {
        int idx = tid + it * 256;
        int row = idx >> LG, ck = idx & (CPR - 1);
        int phys = (ck & ~7) | ((ck ^ row) & 7);
        uint32_t off = (uint32_t)(idx - ck + phys) << 4;
        CP_ASYNC16(bufB + off, Wt + (long long)(bn + row) * KV + ck * 8);
    }

    const int mt0 = blockIdx.y;
    const int gy = gridDim.y;

#define STAGE_A(mt_, dst_)                                                    \
    do {                                                                      \
        const __half* src_ = A + (long long)(mt_) * 128 * KV;                 \
        _Pragma("unroll")                                                     \
        for (int it = 0; it < CPR / 2; it++) {                                \
            int idx = tid + it * 256;                                         \
            int row = idx >> LG, ck = idx & (CPR - 1);                        \
            int phys = (ck & ~7) | ((ck ^ row) & 7);                          \
            uint32_t off = (uint32_t)(idx - ck + phys) << 4;                  \
            CP_ASYNC16((dst_) + off, src_ + (long long)row * KV + ck * 8);    \
        }                                                                     \
    } while (0)

    STAGE_A(mt0, bufA0);
    CP_COMMIT();
    if (mt0 + gy < tiles) STAGE_A(mt0 + gy, bufA1);
    CP_COMMIT();

    const int l15 = lane & 15;
    const int ahi = lane >> 4;
    const int lx = lane & 7;
    const int brow_l = ((lane >> 4) << 3) + lx;
    const int bhi = (lane >> 3) & 1;
    const uint32_t bR = bufB + (uint32_t)(warp_n * 64 + brow_l) * (KV * 2);
    const uint32_t aRowOff = (uint32_t)(warp_m * 32 + l15) * (KV * 2);

    int i = 0;
    for (int mt = mt0; mt < tiles; mt += gy, i++) {
        CP_WAIT(1);
        __syncthreads();

        float acc[2][8][4];
#pragma unroll
        for (int q1 = 0; q1 < 2; q1++)
#pragma unroll
            for (int q2 = 0; q2 < 8; q2++)
#pragma unroll
                for (int q3 = 0; q3 < 4; q3++) acc[q1][q2][q3] = 0.0f;

        const uint32_t aR = ((i & 1) ? bufA1 : bufA0) + aRowOff;
#pragma unroll
        for (int kt = 0; kt < KT; kt++)
#pragma unroll
            for (int s = 0; s < 4; s++) {
                const int cka = kt * 8 + 2 * s + ahi;
                const int ckb = kt * 8 + 2 * s + bhi;
                const uint32_t pa = (uint32_t)((cka & ~7) | ((cka ^ lx) & 7)) << 4;
                const uint32_t pb = (uint32_t)((ckb & ~7) | ((ckb ^ lx) & 7)) << 4;
                uint4 af[2], bf[4];
#pragma unroll
                for (int mt2 = 0; mt2 < 2; mt2++)
                    ldsm4(af[mt2], aR + (uint32_t)(mt2 * 16) * (KV * 2) + pa);
#pragma unroll
                for (int ng = 0; ng < 4; ng++)
                    ldsm4(bf[ng], bR + (uint32_t)(ng * 16) * (KV * 2) + pb);
#pragma unroll
                for (int mt2 = 0; mt2 < 2; mt2++)
#pragma unroll
                    for (int ng = 0; ng < 4; ng++) {
                        mma_fp16(acc[mt2][2 * ng],     af[mt2], bf[ng].x, bf[ng].y);
                        mma_fp16(acc[mt2][2 * ng + 1], af[mt2], bf[ng].z, bf[ng].w);
                    }
            }

#pragma unroll
        for (int mt2 = 0; mt2 < 2; mt2++) {
            long long r0 = (long long)mt * 128 + warp_m * 32 + mt2 * 16 + (lane >> 2);
            long long r1 = r0 + 8;
#pragma unroll
            for (int np = 0; np < 8; np++) {
                int n = bn + warp_n * 64 + np * 8 + 2 * (lane & 3);
                float2 bv = *(const float2*)(bias + n);
                float* d = acc[mt2][np];
                if (r0 < M)
                    *(uint32_t*)(C + r0 * 512 + n) =
                        packh2(fast_sigmoid(d[0] + bv.x), fast_sigmoid(d[1] + bv.y));
                if (r1 < M)
                    *(uint32_t*)(C + r1 * 512 + n) =
                        packh2(fast_sigmoid(d[2] + bv.x), fast_sigmoid(d[3] + bv.y));
            }
        }

        __syncthreads();
        if (mt + 2 * gy < tiles)
            STAGE_A(mt + 2 * gy, (i & 1) ? bufA1 : bufA0);
        CP_COMMIT();
    }
#undef STAGE_A
}

// ------------------------- layers 2/3 kernel (exact r11) -------------------
struct LArgs {
    const __half* A[3];
    void* C[3];
    const float* bias[3];
    const __half* Wt[3];
    int M[3], K[3];
    int tb[4];
    int N;
};

template <bool CF32>
__global__ void __launch_bounds__(256, 2)
mlp_layer(LArgs a)
{
    extern __shared__ char smem[];
    const int t = ((int)blockIdx.y >= a.tb[1]) + ((int)blockIdx.y >= a.tb[2]);
    const int K = a.K[t];
    const int N = a.N;
    const long long bm = (long long)((int)blockIdx.y - a.tb[t]) * 128;
    const int bn = blockIdx.x * 128;
    const __half* Ah = a.A[t];
    const __half* Wt = a.Wt[t];
    const int KT = K >> 6;

    const int tid = threadIdx.x;
    const int lane = tid & 31;
    const int wid = tid >> 5;
    const int warp_m = wid & 3;
    const int warp_n = wid >> 2;

    const uint32_t sb = smem_u32(smem);

    const int crow = tid >> 3;
    const int cchk = tid & 7;
    const __half* pA = Ah + (bm + crow) * (long long)K + cchk * 8;
    const __half* pB = Wt + (long long)(bn + crow) * K + cchk * 8;
    const uint32_t swz = (uint32_t)((cchk ^ (crow & 7)) * 16);
    const uint32_t dA = sb + crow * 128 + swz;
    const uint32_t dB = sb + 16384 + crow * 128 + swz;
    const long long rstep = 32ll * K;

    const int l15 = lane & 15;
    const int ahi = lane >> 4;
    const uint32_t aX = (uint32_t)(lane & 7);
    const uint32_t aBase = sb + (uint32_t)(warp_m * 32 + l15) * 128;
    const int bn_l = warp_n * 64 + ((lane >> 4) << 3) + (lane & 7);
    const int bhi = (lane >> 3) & 1;
    const uint32_t bBase = sb + 16384 + (uint32_t)bn_l * 128;

    float acc[2][8][4];
#pragma unroll
    for (int i = 0; i < 2; i++)
#pragma unroll
        for (int j = 0; j < 8; j++)
#pragma unroll
            for (int q = 0; q < 4; q++) acc[i][j][q] = 0.0f;

#define ISSUE(kt, slot)                                                      \
    do {                                                                     \
        const __half* sA_ = pA + (kt) * 64;                                  \
        const __half* sB_ = pB + (kt) * 64;                                  \
        uint32_t oA_ = dA + (slot) * 32768u;                                 \
        uint32_t oB_ = dB + (slot) * 32768u;                                 \
        _Pragma("unroll")                                                    \
        for (int i = 0; i < 4; i++)                                          \
            CP_ASYNC16(oA_ + i * 4096u, sA_ + i * rstep);                    \
        _Pragma("unroll")                                                    \
        for (int i = 0; i < 4; i++)                                          \
            CP_ASYNC16(oB_ + i * 4096u, sB_ + i * rstep);                    \
    } while (0)

    ISSUE(0, 0);
    CP_COMMIT();
    if (1 < KT) ISSUE(1, 1);
    CP_COMMIT();

    int pf = 2;
    for (int kt = 0; kt < KT; kt++) {
        CP_WAIT(1);
        __syncthreads();
        if (pf < KT) {
            int slot = pf - (pf / 3) * 3;
            ISSUE(pf, slot);
        }
        CP_COMMIT();
        pf++;

        const int cur = kt - (kt / 3) * 3;
        const uint32_t aS = aBase + cur * 32768u;
        const uint32_t bS = bBase + cur * 32768u;
#pragma unroll
        for (int s = 0; s < 4; s++) {
            uint4 af[2];
#pragma unroll
            for (int mt = 0; mt < 2; mt++)
                ldsm4(af[mt], aS + mt * 2048u + ((((uint32_t)(2 * s + ahi)) ^ aX) << 4));
            uint4 bf[4];
#pragma unroll
            for (int ng = 0; ng < 4; ng++)
                ldsm4(bf[ng], bS + ng * 2048u + ((((uint32_t)(2 * s + bhi)) ^ aX) << 4));
#pragma unroll
            for (int mt = 0; mt < 2; mt++)
#pragma unroll
                for (int ng = 0; ng < 4; ng++) {
                    mma_fp16(acc[mt][2 * ng],     af[mt], bf[ng].x, bf[ng].y);
                    mma_fp16(acc[mt][2 * ng + 1], af[mt], bf[ng].z, bf[ng].w);
                }
        }
    }
#undef ISSUE

    const float* bias = a.bias[t];
    const int M = a.M[t];
#pragma unroll
    for (int mt = 0; mt < 2; mt++) {
        long long r0 = bm + warp_m * 32 + mt * 16 + (lane >> 2);
        long long r1 = r0 + 8;
#pragma unroll
        for (int np = 0; np < 8; np++) {
            int n = bn + warp_n * 64 + np * 8 + 2 * (lane & 3);
            float2 bv = *(const float2*)(bias + n);
            float* d = acc[mt][np];
            float s0 = fast_sigmoid(d[0] + bv.x);
            float s1 = fast_sigmoid(d[1] + bv.y);
            float s2 = fast_sigmoid(d[2] + bv.x);
            float s3 = fast_sigmoid(d[3] + bv.y);
            if (CF32) {
                float* C = (float*)a.C[t];
                if (r0 < M) *(float2*)(C + r0 * N + n) = make_float2(s0, s1);
                if (r1 < M) *(float2*)(C + r1 * N + n) = make_float2(s2, s3);
            } else {
                __half* C = (__half*)a.C[t];
                *(uint32_t*)(C + r0 * N + n) = packh2(s0, s1);
                *(uint32_t*)(C + r1 * N + n) = packh2(s2, s3);
            }
        }
    }
}

// ------------------------- host launcher -----------------------------------
extern "C" void kernel_launch(void* const* d_in, const int* in_sizes, int n_in,
                              void* d_out, int out_size)
{
    (void)n_in; (void)out_size;
    const int din[3] = {64, 128, 256};
    int n[3];
    for (int t = 0; t < 3; t++) n[t] = in_sizes[t] / din[t];

    int tiles[3], tb[4];
    tb[0] = 0;
    for (int t = 0; t < 3; t++) {
        tiles[t] = (n[t] + 127) / 128;
        tb[t + 1] = tb[t] + tiles[t];
    }
    long long padrows[3] = {(long long)tiles[0] * 128, (long long)tiles[1] * 128,
                            (long long)tiles[2] * 128};
    long long hb[3] = {0, padrows[0], padrows[0] + padrows[1]};
    long long xoff[3] = {0, padrows[0] * din[0],
                         padrows[0] * din[0] + padrows[1] * din[1]};
    long long outbase[3] = {0, n[0], (long long)n[0] + n[1]};

    const int SMEM = 3 * 32768;
    static cudaStream_t st[3] = {nullptr, nullptr, nullptr};
    static cudaEvent_t evP = nullptr, evJ1 = nullptr, evJ2 = nullptr;
    if (!st[1]) {
        cudaFuncSetAttribute(mlp_layer<false>,
                             cudaFuncAttributeMaxDynamicSharedMemorySize, SMEM);
        cudaFuncSetAttribute(mlp_layer<true>,
                             cudaFuncAttributeMaxDynamicSharedMemorySize, SMEM);
        cudaFuncSetAttribute(mlp_l1<64>,
                             cudaFuncAttributeMaxDynamicSharedMemorySize, 3 * 256 * 64);
        cudaFuncSetAttribute(mlp_l1<128>,
                             cudaFuncAttributeMaxDynamicSharedMemorySize, 3 * 256 * 128);
        cudaFuncSetAttribute(mlp_l1<256>,
                             cudaFuncAttributeMaxDynamicSharedMemorySize, 3 * 256 * 256);
        st[0] = 0;
        cudaStreamCreateWithFlags(&st[1], cudaStreamNonBlocking);
        cudaStreamCreateWithFlags(&st[2], cudaStreamNonBlocking);
        cudaEventCreateWithFlags(&evP, cudaEventDisableTiming);
        cudaEventCreateWithFlags(&evJ1, cudaEventDisableTiming);
        cudaEventCreateWithFlags(&evJ2, cudaEventDisableTiming);
    }

    __half *xh, *h1, *h2, *wt;
    cudaGetSymbolAddress((void**)&xh, g_x);
    cudaGetSymbolAddress((void**)&h1, g_h1);
    cudaGetSymbolAddress((void**)&h2, g_h2);
    cudaGetSymbolAddress((void**)&wt, g_Wt);

    // ---- prep: transpose weights + convert inputs (default stream) ----
    PrepArgs pa;
    long long woff[9];
    {
        long long w = 0;
        int tbt = 0;
        for (int t = 0; t < 3; t++) {
            int Ks[3] = {din[t], 512, 512};
            int Ns[3] = {512, 512, 256};
            for (int l = 0; l < 3; l++) {
                int idx = t * 3 + l;
                pa.W[idx] = (const float*)d_in[4 + 6 * t + 2 * l];
                pa.wtoff[idx] = w;
                woff[idx] = w;
                pa.K[idx] = Ks[l];
                pa.N[idx] = Ns[l];
                pa.tbase[idx] = tbt;
                tbt += (Ks[l] / 32) * (Ns[l] / 32);
                w += (long long)Ks[l] * Ns[l];
            }
        }
        pa.tbase[9] = tbt;
        pa.c1 = n[0] * din[0] / 4;
        pa.c2 = pa.c1 + n[1] * din[1] / 4;
        pa.c3 = pa.c2 + n[2] * din[2] / 4;
        for (int t = 0; t < 3; t++) {
            pa.xs[t] = (const float*)d_in[t];
            pa.xd[t] = xh + xoff[t];
        }
        int cvtb = (pa.c3 + 255) / 256;
        prep_kernel<<<tbt + cvtb, 256>>>(pa);
    }

    // ---- fork: l1 launches for types 1,2 onto side streams ----
    cudaEventRecord(evP, st[0]);
    cudaStreamWaitEvent(st[1], evP, 0);
    cudaStreamWaitEvent(st[2], evP, 0);

    {
        int gy0 = tiles[0] < 74 ? tiles[0] : 74;
        int gy1 = tiles[1] < 74 ? tiles[1] : 74;
        int gy2 = tiles[2] < 37 ? tiles[2] : 37;
        mlp_l1<64><<<dim3(4, gy0), 256, 3 * 256 * 64, st[0]>>>(
            xh + xoff[0], h1 + hb[0] * 512, (const float*)d_in[5],
            wt + woff[0], n[0], tiles[0]);
        mlp_l1<128><<<dim3(4, gy1), 256, 3 * 256 * 128, st[1]>>>(
            xh + xoff[1], h1 + hb[1] * 512, (const float*)d_in[11],
            wt + woff[3], n[1], tiles[1]);
        mlp_l1<256><<<dim3(4, gy2), 256, 3 * 256 * 256, st[2]>>>(
            xh + xoff[2], h1 + hb[2] * 512, (const float*)d_in[17],
            wt + woff[6], n[2], tiles[2]);
    }

    // ---- join side streams before l2 ----
    cudaEventRecord(evJ1, st[1]);
    cudaEventRecord(evJ2, st[2]);
    cudaStreamWaitEvent(st[0], evJ1, 0);
    cudaStreamWaitEvent(st[0], evJ2, 0);

    // ---- layers 2 / 3 (merged, exact r11) ----
    LArgs a;
    for (int i = 0; i < 4; i++) a.tb[i] = tb[i];

    a.N = 512;
    for (int t = 0; t < 3; t++) {
        a.A[t] = h1 + hb[t] * 512;
        a.C[t] = h2 + hb[t] * 512;
        a.bias[t] = (const float*)d_in[7 + 6 * t];
        a.Wt[t] = wt + woff[t * 3 + 1];
        a.M[t] = n[t];
        a.K[t] = 512;
    }
    mlp_layer<false><<<dim3(4, tb[3]), 256, SMEM>>>(a);

    a.N = 256;
    for (int t = 0; t < 3; t++) {
        a.A[t] = h2 + hb[t] * 512;
        a.C[t] = (float*)d_out + outbase[t] * 256;
        a.bias[t] = (const float*)d_in[9 + 6 * t];
        a.Wt[t] = wt + woff[t * 3 + 2];
        a.M[t] = n[t];
        a.K[t] = 512;
    }
    mlp_layer<true><<<dim3(2, tb[3]), 256, SMEM>>>(a);
}